// round 17
// baseline (speedup 1.0000x reference)
#include <cuda_runtime.h>
#include <cuda_fp16.h>
#include <mma.h>
#include <math.h>

using namespace nvcuda;

// Problem constants
#define B   32
#define C   512
#define HW  196          // 14*14
#define D   8192
#define KP  208          // HW padded to 13*16
#define BC  (B * C)      // 16384
#define LDS2 68          // stage row stride (floats)
#define STAGE_F (64 * LDS2)              // floats per batch stage
// K-halved tiles: half0 = 112 cols (7 chunks), half1 = 96 cols (6 chunks)
#define LDKH 120         // half-tile smem row stride (elems), %8==0
#define TILE_H (64 * LDKH)               // elems per half tile (7680)
#define SMEM_DYN (2*TILE_H*2 + 4*STAGE_F*4)   // 30720 + 69632 = 100352
#define GTHR 512         // gram threads per CTA

// ---------------- device scratch (no allocations allowed) ----------------
__device__ int   g_h[2][C];
__device__ float g_s[2][C];
__device__ __align__(32) __half g_Xh[(size_t)BC * KP];   // fp16 copy of x (K-padded)
__device__ float g_Yt[(size_t)D * B];           // [d][b]  (b innermost)
__device__ float g_Ys[(size_t)B * D];           // signed-sqrt values, [b][d]
__device__ float g_norm[B];                      // per-batch sum of squares

// ---------------- 0. dummy: positions gram_scatter at global launch index 3 ----------------
__global__ void dummy_kernel() {}

// ---------------- 1. fused: fp16-pack x, extract (h,s), zero Yt/norm ----------------
__global__ void setup_kernel(const float* __restrict__ x,
                             const float* __restrict__ S1,
                             const float* __restrict__ S2) {
    int bx = blockIdx.x;
    int t  = threadIdx.x;
    if (bx < 1024) {
        // ---- prep: 16 x-rows per block, convert to fp16 ----
        int base = bx * 16;
        for (int e = t; e < 16 * KP; e += 256) {
            int r = e / KP, k = e - r * KP;
            int bc = base + r;
            float v = (k < HW) ? x[(size_t)bc * HW + k] : 0.f;
            g_Xh[(size_t)bc * KP + k] = __float2half(v);
        }
        return;
    }
    if (bx < 1024 + 2048) {
        // ---- extract: 2 blocks per sketch row; 4 independent loads (MLP=4) ----
        int q    = bx - 1024;
        int row  = q >> 1;
        int half = q & 1;
        int mat = row >> 9;
        int r   = row & (C - 1);
        const float4* p = (const float4*)((mat ? S2 : S1) + (size_t)r * D) + half * 1024;
        float4 v[4];
        #pragma unroll
        for (int u = 0; u < 4; u++) v[u] = p[t + u * 256];
        int   idx = -1;
        float sg  = 0.f;
        #pragma unroll
        for (int u = 0; u < 4; u++) {
            int c = half * 4096 + 4 * (t + u * 256);
            if (fabsf(v[u].x) > 0.5f) { idx = c + 0; sg = v[u].x; }
            if (fabsf(v[u].y) > 0.5f) { idx = c + 1; sg = v[u].y; }
            if (fabsf(v[u].z) > 0.5f) { idx = c + 2; sg = v[u].z; }
            if (fabsf(v[u].w) > 0.5f) { idx = c + 3; sg = v[u].w; }
        }
        if (idx >= 0) {                          // exactly one thread (whole grid) hits per row
            g_h[mat][r] = idx;
            g_s[mat][r] = sg;
        }
        return;
    }
    // ---- zero Yt (+ norm): 256 blocks x 256 thr x float4 ----
    int zb = bx - 1024 - 2048;
    float4* y4 = (float4*)g_Yt;
    y4[zb * 256 + t] = make_float4(0.f, 0.f, 0.f, 0.f);
    if (zb == 0 && t < B) g_norm[t] = 0.f;
}

// ---------------- 2. Gram (fp16 wmma), 512 thr / 16 warps, M-split 16x16 warp tiles ----
__global__ __launch_bounds__(GTHR, 2) void gram_scatter() {
    int bg = blockIdx.y;                         // batch group: b = bg*4 + bi
    int ti = 0, rem = blockIdx.x;                // upper-triangular tile pair, ti <= tj
    while (rem >= 8 - ti) { rem -= 8 - ti; ti++; }
    int tj = ti + rem;
    bool diag = (ti == tj);

    extern __shared__ __align__(16) __half sm[];
    __half* Ah = sm;                             // 64 x LDKH
    __half* Bh = sm + TILE_H;                    // 64 x LDKH
    float* stage = (float*)(sm + 2 * TILE_H);    // 4 x (64 x LDS2) floats
    __shared__ int   hh[256];
    __shared__ float ss[256];

    int tid  = threadIdx.x;
    int wid  = tid >> 5;         // 0..15
    int r16  = wid >> 2;         // 0..3  -> rows r16*16
    int cb   = wid & 3;          // 0..3  -> cols cb*16

    int gm = ti * 64, gn = tj * 64;
    if (tid < 64) {
        hh[tid]       = g_h[0][gm + tid];        // h1 over row range
        hh[64 + tid]  = g_h[1][gn + tid];        // h2 over col range
        hh[128 + tid] = g_h[0][gn + tid];        // h1 over col range (mirror)
        hh[192 + tid] = g_h[1][gm + tid];        // h2 over row range (mirror)
        ss[tid]       = g_s[0][gm + tid];
        ss[64 + tid]  = g_s[1][gn + tid];
        ss[128 + tid] = g_s[0][gn + tid];
        ss[192 + tid] = g_s[1][gm + tid];
    }

    const __half* Ph = diag ? Ah : Bh;

    #pragma unroll 1
    for (int bi = 0; bi < 4; bi++) {
        int b = bg * 4 + bi;

        wmma::fragment<wmma::accumulator, 16, 16, 16, float> acc;
        wmma::fill_fragment(acc, 0.f);

        #pragma unroll 1
        for (int h = 0; h < 2; h++) {
            int kbase = h * 112;                 // global k offset of this half
            int nvec  = h ? 12 : 14;             // uint4 (8 halfs) per row
            int nch   = h ? 6 : 7;               // 16-wide MMA chunks in this half
            __syncthreads();                     // prev MMA reads done (and hh/ss ready)
            // ---- stage half-tiles ----
            {
                const __half* srcA = g_Xh + ((size_t)b * C + gm) * KP + kbase;
                const __half* srcB = g_Xh + ((size_t)b * C + gn) * KP + kbase;
                int tot = 64 * nvec;
                #pragma unroll 2
                for (int e = tid; e < tot; e += GTHR) {
                    int row = e / nvec, q = e - row * nvec;
                    *(uint4*)&Ah[row * LDKH + q * 8] = *(const uint4*)&srcA[(size_t)row * KP + q * 8];
                    if (!diag)
                        *(uint4*)&Bh[row * LDKH + q * 8] = *(const uint4*)&srcB[(size_t)row * KP + q * 8];
                }
            }
            __syncthreads();

            #pragma unroll
            for (int c = 0; c < 7; c++) {
                if (c >= nch) break;
                int ko = c * 16;
                wmma::fragment<wmma::matrix_a, 16, 16, 16, __half, wmma::row_major> af;
                wmma::fragment<wmma::matrix_b, 16, 16, 16, __half, wmma::col_major> bf;
                wmma::load_matrix_sync(af, &Ah[(r16 * 16) * LDKH + ko], LDKH);
                wmma::load_matrix_sync(bf, &Ph[(cb * 16) * LDKH + ko], LDKH);
                wmma::mma_sync(acc, af, bf, acc);
            }
        }

        float* st = stage + bi * STAGE_F;
        wmma::store_matrix_sync(&st[(r16 * 16) * LDS2 + cb * 16], acc, LDS2, wmma::mem_row_major);
    }
    __syncthreads();

    // ---- scatter: one red.v4 per (pair, orientation) covering 4 batches ----
    float* Ybase = g_Yt + bg * 4;
    #pragma unroll 4
    for (int e = tid; e < 4096; e += GTHR) {
        int r = e >> 6, c = e & 63;
        int off = r * LDS2 + c;
        float v0 = stage[0 * STAGE_F + off];
        float v1 = stage[1 * STAGE_F + off];
        float v2 = stage[2 * STAGE_F + off];
        float v3 = stage[3 * STAGE_F + off];
        int   d1 = (hh[r] + hh[64 + c]) & (D - 1);
        float w1 = ss[r] * ss[64 + c];
        float* p1 = Ybase + (size_t)d1 * B;
        asm volatile("red.global.add.v4.f32 [%0], {%1, %2, %3, %4};"
                     :: "l"(p1), "f"(v0 * w1), "f"(v1 * w1), "f"(v2 * w1), "f"(v3 * w1)
                     : "memory");
        if (!diag) {
            int   d2 = (hh[128 + c] + hh[192 + r]) & (D - 1);
            float w2 = ss[128 + c] * ss[192 + r];
            float* p2 = Ybase + (size_t)d2 * B;
            asm volatile("red.global.add.v4.f32 [%0], {%1, %2, %3, %4};"
                         :: "l"(p2), "f"(v0 * w2), "f"(v1 * w2), "f"(v2 * w2), "f"(v3 * w2)
                         : "memory");
        }
    }
}

// ---------------- 3a. signed sqrt + transpose + per-batch sumsq (coalesced) ----------------
__global__ void sqrt_transpose_kernel() {        // 256 blocks x 256 thr, 32d x 32b tiles
    __shared__ float tile[32][36];
    __shared__ float snorm[B];
    int t  = threadIdx.x;
    int d0 = blockIdx.x * 32;
    if (t < B) snorm[t] = 0.f;
    __syncthreads();

    float4 v = ((const float4*)(g_Yt + (size_t)d0 * B))[t];  // coalesced: 1024 floats
    int dl = t >> 3;             // d within tile
    int b0 = (t & 7) * 4;        // first of 4 consecutive b
    float vv[4] = {v.x, v.y, v.z, v.w};
    #pragma unroll
    for (int k = 0; k < 4; k++) {
        float y  = vv[k];
        float sg = (y > 0.f) ? 1.f : ((y < 0.f) ? -1.f : 0.f);
        float s  = sg * sqrtf(fabsf(y) + 1e-8f);
        tile[b0 + k][dl] = s;
        atomicAdd(&snorm[b0 + k], s * s);
    }
    __syncthreads();
    if (t < B) atomicAdd(&g_norm[t], snorm[t]);
    int b = t >> 3, q = t & 7;
    float4 w = *(float4*)&tile[b][q * 4];
    ((float4*)(g_Ys + (size_t)b * D + d0))[q] = w;
}

// ---------------- 3b. L2 normalize (coalesced) ----------------
__global__ void normalize_kernel(float* __restrict__ out) {  // 256 blocks x 256 thr
    int b  = blockIdx.x >> 3;
    int d0 = (blockIdx.x & 7) * 1024;
    int t  = threadIdx.x;
    float inv = 1.f / fmaxf(sqrtf(g_norm[b]), 1e-12f);
    float4 v = ((const float4*)(g_Ys + (size_t)b * D + d0))[t];
    v.x *= inv; v.y *= inv; v.z *= inv; v.w *= inv;
    ((float4*)(out + (size_t)b * D + d0))[t] = v;
}

// ---------------- launcher ----------------
extern "C" void kernel_launch(void* const* d_in, const int* in_sizes, int n_in,
                              void* d_out, int out_size) {
    const float* x  = nullptr;
    const float* S1 = nullptr;
    const float* S2 = nullptr;
    for (int i = 0; i < n_in; i++) {
        if (in_sizes[i] == B * C * HW) { x = (const float*)d_in[i]; }
        else if (!S1)                  { S1 = (const float*)d_in[i]; }
        else                           { S2 = (const float*)d_in[i]; }
    }
    float* out = (float*)d_out;

    static int smem_set = 0;
    if (!smem_set) {
        cudaFuncSetAttribute(gram_scatter, cudaFuncAttributeMaxDynamicSharedMemorySize, SMEM_DYN);
        smem_set = 1;
    }

    setup_kernel         <<<1024 + 2048 + 256, 256>>>(x, S1, S2);   // idx 0
    dummy_kernel         <<<1, 32>>>();                              // idx 1
    dummy_kernel         <<<1, 32>>>();                              // idx 2
    gram_scatter         <<<dim3(36, 8), GTHR, SMEM_DYN>>>();        // idx 3 <- ncu sample
    sqrt_transpose_kernel<<<256, 256>>>();
    normalize_kernel     <<<256, 256>>>(out);
}